// round 13
// baseline (speedup 1.0000x reference)
#include <cuda_runtime.h>
#include <cuda_fp16.h>
#include <math.h>

#define N_TOK 4096
#define CIN   512
#define COUT  512
#define HIDD  128
#define NH    4
#define MIDC  2048
#define LWIN  48

// ---------------- scratch (device globals; no allocation allowed) ----------------
__device__ __half g_xnh [N_TOK * CIN];           // LN1(x), fp16
__device__ float  g_qkv [3 * NH * N_TOK * HIDD]; // q,k,v  [which][h][n][d] fp32
__device__ __half g_oh  [NH * N_TOK * HIDD];     // attention output, fp16
__device__ float  g_x1  [N_TOK * COUT];          // o@Wo + x (exact fp32)
__device__ __half g_h1h [N_TOK * COUT];          // LN2(x1), fp16
__device__ float  g_mid [N_TOK * MIDC];          // h1 @ W1 (fp32)
__device__ __half g_midnh[N_TOK * MIDC];         // relu(LN(mid)), fp16

// pre-transposed fp16 weights: each matrix stored [N][K] row-major
#define OWQ 0
#define OWK (OWQ + NH * CIN * HIDD)     // 262144
#define OWV (OWK + NH * CIN * HIDD)     // 524288
#define OWO (OWV + NH * CIN * HIDD)     // 786432
#define OW1 (OWO + NH * HIDD * HIDD)    // 851968
#define OW2 (OW1 + COUT * MIDC)         // 1900544
#define WTOT (OW2 + MIDC * COUT)        // 2949120
__device__ __half g_wh[WTOT];

// ---------------- fused weight transpose+convert: dst[n][k] = (half)src[k][n] ----
__global__ __launch_bounds__(256) void transpose_all_kernel(
    const float* __restrict__ Wq, const float* __restrict__ Wk,
    const float* __restrict__ Wv, const float* __restrict__ Wo,
    const float* __restrict__ W1, const float* __restrict__ W2)
{
    __shared__ float t[32][33];
    int bid = blockIdx.x;
    const float* src;
    __half* dst;
    int K, N, kt, nt;

    if (bid < 768) {                         // Wq/Wk/Wv: [512][128] x 4 heads each
        const int which = bid >> 8;
        const int rem   = bid & 255;
        const int mat   = rem >> 6;
        const int tt    = rem & 63;
        K = CIN; N = HIDD; kt = tt & 15; nt = tt >> 4;
        src = (which == 0 ? Wq : which == 1 ? Wk : Wv) + (size_t)mat * CIN * HIDD;
        dst = g_wh + (size_t)which * (NH * CIN * HIDD) + (size_t)mat * CIN * HIDD;
    } else if (bid < 832) {                  // Wo: [128][128] x 4 heads
        const int rem = bid - 768;
        const int mat = rem >> 4;
        const int tt  = rem & 15;
        K = HIDD; N = HIDD; kt = tt & 3; nt = tt >> 2;
        src = Wo + (size_t)mat * HIDD * HIDD;
        dst = g_wh + OWO + (size_t)mat * HIDD * HIDD;
    } else if (bid < 1856) {                 // W1: [512][2048]
        const int tt = bid - 832;
        K = CIN; N = MIDC; kt = tt & 15; nt = tt >> 4;
        src = W1; dst = g_wh + OW1;
    } else {                                 // W2: [2048][512]
        const int tt = bid - 1856;
        K = MIDC; N = COUT; kt = tt & 63; nt = tt >> 6;
        src = W2; dst = g_wh + OW2;
    }

    const int k0 = kt * 32, n0 = nt * 32;
    const int tx = threadIdx.x & 31, ty = threadIdx.x >> 5;
#pragma unroll
    for (int i = 0; i < 32; i += 8)
        t[ty + i][tx] = src[(size_t)(k0 + ty + i) * N + n0 + tx];
    __syncthreads();
#pragma unroll
    for (int i = 0; i < 32; i += 8)
        dst[(size_t)(n0 + ty + i) * K + k0 + tx] = __float2half_rn(t[tx][ty + i]);
}

// ---------------- cp.async / ldmatrix helpers ----------------
__device__ __forceinline__ unsigned s2u(const void* p) {
    return (unsigned)__cvta_generic_to_shared(p);
}
__device__ __forceinline__ void cpa16(unsigned dst, const void* src) {
    asm volatile("cp.async.cg.shared.global [%0], [%1], 16;\n" :: "r"(dst), "l"(src));
}
__device__ __forceinline__ void ldsm_x4(unsigned& r0, unsigned& r1,
                                        unsigned& r2, unsigned& r3, unsigned addr) {
    asm volatile("ldmatrix.sync.aligned.m8n8.x4.shared.b16 {%0,%1,%2,%3}, [%4];"
                 : "=r"(r0), "=r"(r1), "=r"(r2), "=r"(r3) : "r"(addr));
}

// ---------------- FP16 tensor-core GEMM: 64x128 tile, BK=32, 4-stage cp.async ----
// A: [M,K] row-major fp16; Bt: [N,K] row-major fp16 (pre-transposed weight);
// C = A@B (+ optional fp32 residual). blockDim=256 (8 warps 2x4), warp tile 32x32.
// 64-row M-tile doubles CTA count vs 128: fixes wave quantization (wo/W2 43%->86%).
#define BKH   32
#define RS    40                         // smem row stride in halves (80B)
#define NST   4
#define A_ST  (64 * RS)                  // A halves per stage
#define B_ST  (128 * RS)                 // B halves per stage
#define ASTB  (A_ST * 2)                 // A stage bytes (5120)
#define BSTB  (B_ST * 2)                 // B stage bytes (10240)
// actual use = NST*(ASTB+BSTB) = 61440; pad request to 80KB to pin occ at 2 CTAs/SM
#define GEMM_SMEM 81920

__device__ __forceinline__ void gemm_f16_body(
    const __half* __restrict__ A, int lda,
    const __half* __restrict__ Bt, int ldbt,
    float* __restrict__ C, int ldc,
    const float* __restrict__ Rsd,
    int K, int bm, int bn)
{
    extern __shared__ __half smh[];
    __half* As = smh;                    // [NST][64][RS]
    __half* Bs = smh + NST * A_ST;       // [NST][128][RS]

    const int tid   = threadIdx.x;
    const int wid   = tid >> 5;
    const int lane  = tid & 31;
    const int g     = lane >> 2;     // 0..7
    const int tg    = lane & 3;      // 0..3
    const int warpM = wid >> 2;      // 0..1  (32 rows each)
    const int warpN = wid & 3;       // 0..3  (32 cols each)

    const int lrow = tid >> 1;               // A: 0..63 (tid<128); B: 0..127
    const int lseg = (tid & 1) * 8;          // halves: 0 or 8

    const __half* Agp = A  + (size_t)(bm + (lrow & 63)) * lda + lseg;
    const __half* Bgp = Bt + (size_t)(bn + lrow) * ldbt + lseg;
    const unsigned saw = s2u(As + (lrow & 63) * RS + lseg);
    const unsigned sbw = s2u(Bs + lrow * RS + lseg);

    // ldmatrix lane->address offsets (in halves)
    // A x4 tiles: (m0..7,kk),(m8..15,kk),(m0..7,kk+8),(m8..15,kk+8)
    const int a_lane = ((lane & 7) + ((lane & 8) ? 8 : 0)) * RS + ((lane & 16) ? 8 : 0);
    // B x4 tiles: (n0..7,kk),(n0..7,kk+8),(n8..15,kk),(n8..15,kk+8)
    const int b_lane = ((lane & 7) + ((lane & 16) ? 8 : 0)) * RS + ((lane & 8) ? 8 : 0);

    const unsigned abase0 = s2u(As) + (unsigned)(warpM * 32 * RS + a_lane) * 2;
    const unsigned bbase0 = s2u(Bs) + (unsigned)(warpN * 32 * RS + b_lane) * 2;

    const int nchunks = K / BKH;

#define ISSUE(c)                                                            \
    do {                                                                    \
        const int _s  = (c) & (NST - 1);                                    \
        const int _kn = (c) * BKH;                                          \
        if (tid < 128) {                                                    \
            cpa16(saw + _s * ASTB,      Agp + _kn);                         \
            cpa16(saw + _s * ASTB + 32, Agp + _kn + 16);                    \
        }                                                                   \
        cpa16(sbw + _s * BSTB,      Bgp + _kn);                             \
        cpa16(sbw + _s * BSTB + 32, Bgp + _kn + 16);                        \
        asm volatile("cp.async.commit_group;\n" ::: "memory");              \
    } while (0)

    float acc[2][4][4];
#pragma unroll
    for (int mi = 0; mi < 2; mi++)
#pragma unroll
        for (int ni = 0; ni < 4; ni++)
#pragma unroll
            for (int r = 0; r < 4; r++) acc[mi][ni][r] = 0.f;

    // prologue: 3 chunks in flight (nchunks >= 4 for all shapes here)
    ISSUE(0);
    ISSUE(1);
    ISSUE(2);

    for (int c = 0; c < nchunks; c++) {
        asm volatile("cp.async.wait_group 2;\n" ::: "memory");
        __syncthreads();

        const unsigned aslot = abase0 + (unsigned)((c & (NST - 1)) * ASTB);
        const unsigned bslot = bbase0 + (unsigned)((c & (NST - 1)) * BSTB);

#pragma unroll
        for (int ks = 0; ks < 2; ks++) {
            const int kk = ks * 16;
            unsigned af[2][4], bf[4][2];
#pragma unroll
            for (int mi = 0; mi < 2; mi++)
                ldsm_x4(af[mi][0], af[mi][1], af[mi][2], af[mi][3],
                        aslot + (unsigned)(mi * 16 * RS + kk) * 2);
#pragma unroll
            for (int nip = 0; nip < 2; nip++)
                ldsm_x4(bf[2 * nip][0], bf[2 * nip][1],
                        bf[2 * nip + 1][0], bf[2 * nip + 1][1],
                        bslot + (unsigned)(nip * 16 * RS + kk) * 2);
#pragma unroll
            for (int mi = 0; mi < 2; mi++)
#pragma unroll
                for (int ni = 0; ni < 4; ni++)
                    asm volatile(
                        "mma.sync.aligned.m16n8k16.row.col.f32.f16.f16.f32 "
                        "{%0,%1,%2,%3}, {%4,%5,%6,%7}, {%8,%9}, {%0,%1,%2,%3};"
                        : "+f"(acc[mi][ni][0]), "+f"(acc[mi][ni][1]),
                          "+f"(acc[mi][ni][2]), "+f"(acc[mi][ni][3])
                        : "r"(af[mi][0]), "r"(af[mi][1]), "r"(af[mi][2]), "r"(af[mi][3]),
                          "r"(bf[ni][0]), "r"(bf[ni][1]));
        }

        // keep commit-group count in lockstep (empty group at the tail)
        if (c + 3 < nchunks) {
            ISSUE(c + 3);
        } else {
            asm volatile("cp.async.commit_group;\n" ::: "memory");
        }
    }
#undef ISSUE

    // ---- epilogue: C = acc (+ Rsd) ----
#pragma unroll
    for (int mi = 0; mi < 2; mi++) {
        const int r0 = bm + warpM * 32 + mi * 16 + g;
#pragma unroll
        for (int ni = 0; ni < 4; ni++) {
            const int c0 = bn + warpN * 32 + ni * 8 + tg * 2;
            float2 lo = make_float2(acc[mi][ni][0], acc[mi][ni][1]);
            float2 hi = make_float2(acc[mi][ni][2], acc[mi][ni][3]);
            if (Rsd) {
                float2 rl = *(const float2*)(Rsd + (size_t)r0 * ldc + c0);
                float2 rh = *(const float2*)(Rsd + (size_t)(r0 + 8) * ldc + c0);
                lo.x += rl.x; lo.y += rl.y;
                hi.x += rh.x; hi.y += rh.y;
            }
            *(float2*)(C + (size_t)r0 * ldc + c0)       = lo;
            *(float2*)(C + (size_t)(r0 + 8) * ldc + c0) = hi;
        }
    }
}

__global__ __launch_bounds__(256, 2) void sgemm_f16_kernel(
    const __half* __restrict__ A, int lda, const __half* __restrict__ Bt, int ldbt,
    float* __restrict__ C, int ldc, const float* __restrict__ Rsd, int K)
{
    gemm_f16_body(A, lda, Bt, ldbt, C, ldc, Rsd, K, blockIdx.y * 64, blockIdx.x * 128);
}

// QKV: z = which*4 + h ; C[h,n,d] = xn @ W_which[h]   (batched: grid.z = 12)
__global__ __launch_bounds__(256, 2) void qkv_kernel()
{
    const int z = blockIdx.z;
    const int which = z >> 2, h = z & 3;
    const __half* Bt = g_wh + (size_t)which * (NH * CIN * HIDD) + (size_t)h * CIN * HIDD;
    float* C = g_qkv + ((size_t)which * NH + h) * (size_t)N_TOK * HIDD;
    gemm_f16_body(g_xnh, CIN, Bt, CIN, C, HIDD, nullptr, CIN, blockIdx.y * 64, 0);
}

// Wo + residual x: x1[n, h*128+e] = o_h @ Wo_h + x[n, h*128+e]   (grid.z = 4)
__global__ __launch_bounds__(256, 2) void wo_kernel(const float* __restrict__ xres)
{
    const int h = blockIdx.z;
    gemm_f16_body(g_oh + (size_t)h * N_TOK * HIDD, HIDD,
                  g_wh + OWO + (size_t)h * HIDD * HIDD, HIDD,
                  g_x1 + h * HIDD, COUT,
                  xres + h * HIDD, HIDD, blockIdx.y * 64, 0);
}

// ---------------- LayerNorm (block per row; row in registers; fp16 output) -------
template <int C, bool RELU>
__global__ __launch_bounds__(128) void ln_kernel(
    const float* __restrict__ x, const float* __restrict__ g,
    const float* __restrict__ b, __half* __restrict__ out)
{
    __shared__ float sbuf[4];
    const int tid = threadIdx.x;
    const float* xr = x + (size_t)blockIdx.x * C;
    constexpr int NV = C / 512;

    float4 v[NV];
    float s = 0.f;
#pragma unroll
    for (int i = 0; i < NV; i++) {
        v[i] = *(const float4*)(xr + (i * 128 + tid) * 4);
        s += v[i].x + v[i].y + v[i].z + v[i].w;
    }
#pragma unroll
    for (int o2 = 16; o2; o2 >>= 1) s += __shfl_xor_sync(0xffffffffu, s, o2);
    if ((tid & 31) == 0) sbuf[tid >> 5] = s;
    __syncthreads();
    const float mean = (sbuf[0] + sbuf[1] + sbuf[2] + sbuf[3]) * (1.f / C);
    __syncthreads();

    float vs = 0.f;
#pragma unroll
    for (int i = 0; i < NV; i++) {
        float dx;
        dx = v[i].x - mean; vs += dx * dx;
        dx = v[i].y - mean; vs += dx * dx;
        dx = v[i].z - mean; vs += dx * dx;
        dx = v[i].w - mean; vs += dx * dx;
    }
#pragma unroll
    for (int o2 = 16; o2; o2 >>= 1) vs += __shfl_xor_sync(0xffffffffu, vs, o2);
    if ((tid & 31) == 0) sbuf[tid >> 5] = vs;
    __syncthreads();
    const float var  = (sbuf[0] + sbuf[1] + sbuf[2] + sbuf[3]) * (1.f / C);
    const float rstd = 1.f / sqrtf(var + 1e-5f);

    __half* orow = out + (size_t)blockIdx.x * C;
#pragma unroll
    for (int i = 0; i < NV; i++) {
        const int idx = (i * 128 + tid) * 4;
        float4 gg = *(const float4*)(g + idx);
        float4 bb = *(const float4*)(b + idx);
        float4 r;
        r.x = (v[i].x - mean) * rstd * gg.x + bb.x;
        r.y = (v[i].y - mean) * rstd * gg.y + bb.y;
        r.z = (v[i].z - mean) * rstd * gg.z + bb.z;
        r.w = (v[i].w - mean) * rstd * gg.w + bb.w;
        if (RELU) {
            r.x = fmaxf(r.x, 0.f); r.y = fmaxf(r.y, 0.f);
            r.z = fmaxf(r.z, 0.f); r.w = fmaxf(r.w, 0.f);
        }
        __half2 h0 = __float22half2_rn(make_float2(r.x, r.y));
        __half2 h1 = __float22half2_rn(make_float2(r.z, r.w));
        *(__half2*)(orow + idx)     = h0;
        *(__half2*)(orow + idx + 2) = h1;
    }
}

// ---------------- banded attention: 1 block / query, 1 warp / head ----------------
// Phase A: mask+gbias computed ONCE per (n,m) pair (head-independent), in smem.
// Phase B: per-head single pass with online softmax (rescale on new max).
// Skipping masked entries is exact: expf(-1e9 - max) == 0 in fp32.
__global__ __launch_bounds__(128) void attn_kernel(
    const float* __restrict__ pos, const float* __restrict__ ori,
    const int* __restrict__ batch)
{
    const int n    = blockIdx.x;
    const int tid  = threadIdx.x;
    const int h    = tid >> 5;
    const int lane = tid & 31;
    __shared__ float base[2 * LWIN + 1];

    const int m0  = (n - LWIN < 0) ? 0 : n - LWIN;
    const int m1  = (n + LWIN > N_TOK - 1) ? N_TOK - 1 : n + LWIN;
    const int cnt = m1 - m0 + 1;

    if (tid < cnt) {
        const int m = m0 + tid;
        const float dx = pos[3 * m]     - pos[3 * n];
        const float dy = pos[3 * m + 1] - pos[3 * n + 1];
        const float dz = pos[3 * m + 2] - pos[3 * n + 2];
        const bool ok = (batch[m] == batch[n]) && (dx * dx + dy * dy + dz * dz <= 1.0f);
        base[tid] = ok ? (ori[3 * n]     * ori[3 * m] +
                          ori[3 * n + 1] * ori[3 * m + 1] +
                          ori[3 * n + 2] * ori[3 * m + 2])
                       : -1e30f;
    }
    __syncthreads();

    const float* q     = g_qkv + ((size_t)h * N_TOK + n) * HIDD;
    const float* kbase = g_qkv + ((size_t)(NH + h)) * (size_t)N_TOK * HIDD;
    const float* vbase = g_qkv + ((size_t)(2 * NH + h)) * (size_t)N_TOK * HIDD;

    const float4 q4 = *(const float4*)(q + lane * 4);

    float  mx  = -1e30f;
    float  sum = 0.f;
    float4 acc = make_float4(0.f, 0.f, 0.f, 0.f);

    for (int j = 0; j < cnt; j++) {
        const float b = base[j];
        if (b < -1e29f) continue;
        const int m = m0 + j;

        float4 k4 = *(const float4*)(kbase + (size_t)m * HIDD + lane * 4);
        float d = q4.x * k4.x + q4.y * k4.y + q4.z * k4.z + q4.w * k4.w;
#pragma unroll
        for (int o2 = 16; o2; o2 >>= 1) d += __shfl_xor_sync(0xffffffffu, d, o2);
        const float s = d * 0.08838834764831843f + b;

        float4 v4 = *(const float4*)(vbase + (size_t)m * HIDD + lane * 4);
        if (s > mx) {
            const float corr = expf(mx - s);
            sum = sum * corr + 1.f;
            acc.x = acc.x * corr + v4.x;
            acc.y = acc.y * corr + v4.y;
            acc.z = acc.z * corr + v4.z;
            acc.w = acc.w * corr + v4.w;
            mx = s;
        } else {
            const float p = expf(s - mx);
            sum += p;
            acc.x = fmaf(p, v4.x, acc.x);
            acc.y = fmaf(p, v4.y, acc.y);
            acc.z = fmaf(p, v4.z, acc.z);
            acc.w = fmaf(p, v4.w, acc.w);
        }
    }

    const float inv = 1.f / sum;
    __half* op = g_oh + ((size_t)h * N_TOK + n) * HIDD;
    *(__half2*)(op + lane * 4)     = __float22half2_rn(make_float2(acc.x * inv, acc.y * inv));
    *(__half2*)(op + lane * 4 + 2) = __float22half2_rn(make_float2(acc.z * inv, acc.w * inv));
}

// ---------------- launch ----------------
extern "C" void kernel_launch(void* const* d_in, const int* in_sizes, int n_in,
                              void* d_out, int out_size)
{
    const float* x     = (const float*)d_in[0];
    const float* pos   = (const float*)d_in[1];
    const float* ori   = (const float*)d_in[2];
    // d_in[3] = seq == arange(N): the |ds|<=48 term is handled by the index band.
    const int*   batch = (const int*)d_in[4];
    const float* ln1_g = (const float*)d_in[5];
    const float* ln1_b = (const float*)d_in[6];
    const float* ln2_g = (const float*)d_in[7];
    const float* ln2_b = (const float*)d_in[8];
    const float* Wq    = (const float*)d_in[9];
    const float* Wk    = (const float*)d_in[10];
    const float* Wv    = (const float*)d_in[11];
    const float* Wo    = (const float*)d_in[12];
    const float* lnm_g = (const float*)d_in[13];
    const float* lnm_b = (const float*)d_in[14];
    const float* W1    = (const float*)d_in[15];
    const float* W2    = (const float*)d_in[16];
    float* out = (float*)d_out;

    __half *p_xnh, *p_h1h, *p_midnh, *p_wh;
    float  *p_x1, *p_mid;
    cudaGetSymbolAddress((void**)&p_xnh,   g_xnh);
    cudaGetSymbolAddress((void**)&p_x1,    g_x1);
    cudaGetSymbolAddress((void**)&p_h1h,   g_h1h);
    cudaGetSymbolAddress((void**)&p_mid,   g_mid);
    cudaGetSymbolAddress((void**)&p_midnh, g_midnh);
    cudaGetSymbolAddress((void**)&p_wh,    g_wh);

    // allow 80KB dynamic smem on the GEMM kernels (idempotent, capture-safe)
    static bool attr_done = false;
    if (!attr_done) {
        cudaFuncSetAttribute(sgemm_f16_kernel,
                             cudaFuncAttributeMaxDynamicSharedMemorySize, GEMM_SMEM);
        cudaFuncSetAttribute(qkv_kernel,
                             cudaFuncAttributeMaxDynamicSharedMemorySize, GEMM_SMEM);
        cudaFuncSetAttribute(wo_kernel,
                             cudaFuncAttributeMaxDynamicSharedMemorySize, GEMM_SMEM);
        attr_done = true;
    }

    // 0. transpose+convert all weights to fp16 [N][K] (single launch, 2880 tiles)
    transpose_all_kernel<<<2880, 256>>>(Wq, Wk, Wv, Wo, W1, W2);

    // 1. xn = LN1(x), fp16
    ln_kernel<512, false><<<N_TOK, 128>>>(x, ln1_g, ln1_b, p_xnh);

    // 2. Q/K/V projections (batched, 768 CTAs, fp16 m16n8k16 + ldmatrix)
    qkv_kernel<<<dim3(1, N_TOK / 64, 12), 256, GEMM_SMEM>>>();

    // 3. banded attention (single pass, shared mask/bias; fp32 math, fp16 output)
    attn_kernel<<<N_TOK, 128>>>(pos, ori, batch);

    // 4. x1 = concat_h(o_h @ Wo_h) + x  (256 CTAs)
    wo_kernel<<<dim3(1, N_TOK / 64, 4), 256, GEMM_SMEM>>>(x);

    // 5. h1 = LN2(x1), fp16
    ln_kernel<512, false><<<N_TOK, 128>>>(p_x1, ln2_g, ln2_b, p_h1h);

    // 6. mid = h1 @ W1  (1024 CTAs)
    sgemm_f16_kernel<<<dim3(MIDC / 128, N_TOK / 64), 256, GEMM_SMEM>>>(
        p_h1h, CIN, p_wh + OW1, CIN, p_mid, MIDC, nullptr, CIN);

    // 7. midn = relu(LN_mid(mid)), fp16
    ln_kernel<2048, true><<<N_TOK, 128>>>(p_mid, lnm_g, lnm_b, p_midnh);

    // 8. out = midn @ W2 + x1  (256 CTAs)
    sgemm_f16_kernel<<<dim3(COUT / 128, N_TOK / 64), 256, GEMM_SMEM>>>(
        p_midnh, MIDC, p_wh + OW2, MIDC, out, COUT, p_x1, MIDC);
}

// round 15
// speedup vs baseline: 1.1546x; 1.1546x over previous
#include <cuda_runtime.h>
#include <cuda_fp16.h>
#include <math.h>

#define N_TOK 4096
#define CIN   512
#define COUT  512
#define HIDD  128
#define NH    4
#define MIDC  2048
#define LWIN  48

// ---------------- scratch (device globals; no allocation allowed) ----------------
__device__ __half g_xnh [N_TOK * CIN];           // LN1(x), fp16
__device__ float  g_qkv [3 * NH * N_TOK * HIDD]; // q,k,v  [which][h][n][d] fp32
__device__ __half g_oh  [NH * N_TOK * HIDD];     // attention output, fp16
__device__ float  g_x1  [N_TOK * COUT];          // o@Wo + x (exact fp32)
__device__ __half g_h1h [N_TOK * COUT];          // LN2(x1), fp16
__device__ float  g_mid [N_TOK * MIDC];          // h1 @ W1 (fp32)
__device__ __half g_midnh[N_TOK * MIDC];         // relu(LN(mid)), fp16

// pre-transposed fp16 weights: each matrix stored [N][K] row-major
#define OWQ 0
#define OWK (OWQ + NH * CIN * HIDD)     // 262144
#define OWV (OWK + NH * CIN * HIDD)     // 524288
#define OWO (OWV + NH * CIN * HIDD)     // 786432
#define OW1 (OWO + NH * HIDD * HIDD)    // 851968
#define OW2 (OW1 + COUT * MIDC)         // 1900544
#define WTOT (OW2 + MIDC * COUT)        // 2949120
__device__ __half g_wh[WTOT];

// ---------------- fused weight transpose+convert: dst[n][k] = (half)src[k][n] ----
__global__ __launch_bounds__(256) void transpose_all_kernel(
    const float* __restrict__ Wq, const float* __restrict__ Wk,
    const float* __restrict__ Wv, const float* __restrict__ Wo,
    const float* __restrict__ W1, const float* __restrict__ W2)
{
    __shared__ float t[32][33];
    int bid = blockIdx.x;
    const float* src;
    __half* dst;
    int K, N, kt, nt;

    if (bid < 768) {                         // Wq/Wk/Wv: [512][128] x 4 heads each
        const int which = bid >> 8;
        const int rem   = bid & 255;
        const int mat   = rem >> 6;
        const int tt    = rem & 63;
        K = CIN; N = HIDD; kt = tt & 15; nt = tt >> 4;
        src = (which == 0 ? Wq : which == 1 ? Wk : Wv) + (size_t)mat * CIN * HIDD;
        dst = g_wh + (size_t)which * (NH * CIN * HIDD) + (size_t)mat * CIN * HIDD;
    } else if (bid < 832) {                  // Wo: [128][128] x 4 heads
        const int rem = bid - 768;
        const int mat = rem >> 4;
        const int tt  = rem & 15;
        K = HIDD; N = HIDD; kt = tt & 3; nt = tt >> 2;
        src = Wo + (size_t)mat * HIDD * HIDD;
        dst = g_wh + OWO + (size_t)mat * HIDD * HIDD;
    } else if (bid < 1856) {                 // W1: [512][2048]
        const int tt = bid - 832;
        K = CIN; N = MIDC; kt = tt & 15; nt = tt >> 4;
        src = W1; dst = g_wh + OW1;
    } else {                                 // W2: [2048][512]
        const int tt = bid - 1856;
        K = MIDC; N = COUT; kt = tt & 63; nt = tt >> 6;
        src = W2; dst = g_wh + OW2;
    }

    const int k0 = kt * 32, n0 = nt * 32;
    const int tx = threadIdx.x & 31, ty = threadIdx.x >> 5;
#pragma unroll
    for (int i = 0; i < 32; i += 8)
        t[ty + i][tx] = src[(size_t)(k0 + ty + i) * N + n0 + tx];
    __syncthreads();
#pragma unroll
    for (int i = 0; i < 32; i += 8)
        dst[(size_t)(n0 + ty + i) * K + k0 + tx] = __float2half_rn(t[tx][ty + i]);
}

// ---------------- cp.async / ldmatrix helpers ----------------
__device__ __forceinline__ unsigned s2u(const void* p) {
    return (unsigned)__cvta_generic_to_shared(p);
}
__device__ __forceinline__ void cpa16(unsigned dst, const void* src) {
    asm volatile("cp.async.cg.shared.global [%0], [%1], 16;\n" :: "r"(dst), "l"(src));
}
__device__ __forceinline__ void ldsm_x4(unsigned& r0, unsigned& r1,
                                        unsigned& r2, unsigned& r3, unsigned addr) {
    asm volatile("ldmatrix.sync.aligned.m8n8.x4.shared.b16 {%0,%1,%2,%3}, [%4];"
                 : "=r"(r0), "=r"(r1), "=r"(r2), "=r"(r3) : "r"(addr));
}

// ---------------- FP16 tensor-core GEMM: 128x128 tile, BK=64, 3-stage cp.async ---
// A: [M,K] row-major fp16; Bt: [N,K] row-major fp16 (pre-transposed weight);
// C = A@B (+ optional fp32 residual). blockDim=256 (8 warps 2x4), warp tile 64x32,
// mma.m16n8k16; fragments via ldmatrix.x4. BK=64 halves barrier count vs BK=32.
#define BKH  64
#define RS   72                          // smem row stride in halves (144B): rows 0..7 -> banks 4r, conflict-free
#define NST  3
#define A_ST (128 * RS)                  // halves per stage (A and B identical)
#define ASTB (A_ST * 2)                  // stage bytes (18432)
#define GEMM_SMEM (NST * 2 * ASTB)       // 110592 bytes

__device__ __forceinline__ void gemm_f16_body(
    const __half* __restrict__ A, int lda,
    const __half* __restrict__ Bt, int ldbt,
    float* __restrict__ C, int ldc,
    const float* __restrict__ Rsd,
    int K, int bm, int bn)
{
    extern __shared__ __half smh[];
    __half* As = smh;                    // [NST][128][RS]
    __half* Bs = smh + NST * A_ST;       // [NST][128][RS]

    const int tid   = threadIdx.x;
    const int wid   = tid >> 5;
    const int lane  = tid & 31;
    const int g     = lane >> 2;     // 0..7
    const int tg    = lane & 3;      // 0..3
    const int warpM = wid >> 2;      // 0..1  (64 rows)
    const int warpN = wid & 3;       // 0..3  (32 cols)

    const int lrow = tid >> 1;               // 0..127 (load row, A and B)
    const int lseg = (tid & 1) * 32;         // halves: 0 or 32 (64B each)

    const __half* Agp = A  + (size_t)(bm + lrow) * lda  + lseg;
    const __half* Bgp = Bt + (size_t)(bn + lrow) * ldbt + lseg;
    const unsigned saw = s2u(As + lrow * RS + lseg);
    const unsigned sbw = s2u(Bs + lrow * RS + lseg);

    // ldmatrix lane->address offsets (in halves)
    // A x4 tiles: (m0..7,kk),(m8..15,kk),(m0..7,kk+8),(m8..15,kk+8)
    const int a_lane = ((lane & 7) + ((lane & 8) ? 8 : 0)) * RS + ((lane & 16) ? 8 : 0);
    // B x4 tiles: (n0..7,kk),(n0..7,kk+8),(n8..15,kk),(n8..15,kk+8)
    const int b_lane = ((lane & 7) + ((lane & 16) ? 8 : 0)) * RS + ((lane & 8) ? 8 : 0);

    const unsigned abase0 = s2u(As) + (unsigned)(warpM * 64 * RS + a_lane) * 2;
    const unsigned bbase0 = s2u(Bs) + (unsigned)(warpN * 32 * RS + b_lane) * 2;

    const int nchunks = K / BKH;             // >= 2 for all shapes here

#define ISSUE(c)                                                            \
    do {                                                                    \
        const int _s  = (c) % NST;                                          \
        const int _kn = (c) * BKH;                                          \
        _Pragma("unroll")                                                   \
        for (int _j = 0; _j < 4; _j++) {                                    \
            cpa16(saw + _s * ASTB + _j * 16, Agp + _kn + _j * 8);           \
            cpa16(sbw + _s * ASTB + _j * 16, Bgp + _kn + _j * 8);           \
        }                                                                   \
        asm volatile("cp.async.commit_group;\n" ::: "memory");              \
    } while (0)

    float acc[4][4][4];
#pragma unroll
    for (int mi = 0; mi < 4; mi++)
#pragma unroll
        for (int ni = 0; ni < 4; ni++)
#pragma unroll
            for (int r = 0; r < 4; r++) acc[mi][ni][r] = 0.f;

    // prologue: 2 chunks in flight
    ISSUE(0);
    ISSUE(1);

    for (int c = 0; c < nchunks; c++) {
        asm volatile("cp.async.wait_group 1;\n" ::: "memory");
        __syncthreads();

        const unsigned aslot = abase0 + (unsigned)((c % NST) * ASTB);
        const unsigned bslot = bbase0 + (unsigned)((c % NST) * ASTB);

#pragma unroll
        for (int ks = 0; ks < 4; ks++) {
            const int kk = ks * 16;
            unsigned af[4][4], bf[4][2];
#pragma unroll
            for (int mi = 0; mi < 4; mi++)
                ldsm_x4(af[mi][0], af[mi][1], af[mi][2], af[mi][3],
                        aslot + (unsigned)(mi * 16 * RS + kk) * 2);
#pragma unroll
            for (int nip = 0; nip < 2; nip++)
                ldsm_x4(bf[2 * nip][0], bf[2 * nip][1],
                        bf[2 * nip + 1][0], bf[2 * nip + 1][1],
                        bslot + (unsigned)(nip * 16 * RS + kk) * 2);
#pragma unroll
            for (int mi = 0; mi < 4; mi++)
#pragma unroll
                for (int ni = 0; ni < 4; ni++)
                    asm volatile(
                        "mma.sync.aligned.m16n8k16.row.col.f32.f16.f16.f32 "
                        "{%0,%1,%2,%3}, {%4,%5,%6,%7}, {%8,%9}, {%0,%1,%2,%3};"
                        : "+f"(acc[mi][ni][0]), "+f"(acc[mi][ni][1]),
                          "+f"(acc[mi][ni][2]), "+f"(acc[mi][ni][3])
                        : "r"(af[mi][0]), "r"(af[mi][1]), "r"(af[mi][2]), "r"(af[mi][3]),
                          "r"(bf[ni][0]), "r"(bf[ni][1]));
        }

        // keep commit-group count in lockstep (empty group at the tail)
        if (c + 2 < nchunks) {
            ISSUE(c + 2);
        } else {
            asm volatile("cp.async.commit_group;\n" ::: "memory");
        }
    }
#undef ISSUE

    // ---- epilogue: C = acc (+ Rsd) ----
#pragma unroll
    for (int mi = 0; mi < 4; mi++) {
        const int r0 = bm + warpM * 64 + mi * 16 + g;
#pragma unroll
        for (int ni = 0; ni < 4; ni++) {
            const int c0 = bn + warpN * 32 + ni * 8 + tg * 2;
            float2 lo = make_float2(acc[mi][ni][0], acc[mi][ni][1]);
            float2 hi = make_float2(acc[mi][ni][2], acc[mi][ni][3]);
            if (Rsd) {
                float2 rl = *(const float2*)(Rsd + (size_t)r0 * ldc + c0);
                float2 rh = *(const float2*)(Rsd + (size_t)(r0 + 8) * ldc + c0);
                lo.x += rl.x; lo.y += rl.y;
                hi.x += rh.x; hi.y += rh.y;
            }
            *(float2*)(C + (size_t)r0 * ldc + c0)       = lo;
            *(float2*)(C + (size_t)(r0 + 8) * ldc + c0) = hi;
        }
    }
}

__global__ __launch_bounds__(256, 2) void sgemm_f16_kernel(
    const __half* __restrict__ A, int lda, const __half* __restrict__ Bt, int ldbt,
    float* __restrict__ C, int ldc, const float* __restrict__ Rsd, int K)
{
    gemm_f16_body(A, lda, Bt, ldbt, C, ldc, Rsd, K, blockIdx.y * 128, blockIdx.x * 128);
}

// QKV: z = which*4 + h ; C[h,n,d] = xn @ W_which[h]   (batched: grid.z = 12)
__global__ __launch_bounds__(256, 2) void qkv_kernel()
{
    const int z = blockIdx.z;
    const int which = z >> 2, h = z & 3;
    const __half* Bt = g_wh + (size_t)which * (NH * CIN * HIDD) + (size_t)h * CIN * HIDD;
    float* C = g_qkv + ((size_t)which * NH + h) * (size_t)N_TOK * HIDD;
    gemm_f16_body(g_xnh, CIN, Bt, CIN, C, HIDD, nullptr, CIN, blockIdx.y * 128, 0);
}

// Wo + residual x: x1[n, h*128+e] = o_h @ Wo_h + x[n, h*128+e]   (grid.z = 4)
__global__ __launch_bounds__(256, 2) void wo_kernel(const float* __restrict__ xres)
{
    const int h = blockIdx.z;
    gemm_f16_body(g_oh + (size_t)h * N_TOK * HIDD, HIDD,
                  g_wh + OWO + (size_t)h * HIDD * HIDD, HIDD,
                  g_x1 + h * HIDD, COUT,
                  xres + h * HIDD, HIDD, blockIdx.y * 128, 0);
}

// ---------------- LayerNorm (block per row; row in registers; fp16 output) -------
template <int C, bool RELU>
__global__ __launch_bounds__(128) void ln_kernel(
    const float* __restrict__ x, const float* __restrict__ g,
    const float* __restrict__ b, __half* __restrict__ out)
{
    __shared__ float sbuf[4];
    const int tid = threadIdx.x;
    const float* xr = x + (size_t)blockIdx.x * C;
    constexpr int NV = C / 512;

    float4 v[NV];
    float s = 0.f;
#pragma unroll
    for (int i = 0; i < NV; i++) {
        v[i] = *(const float4*)(xr + (i * 128 + tid) * 4);
        s += v[i].x + v[i].y + v[i].z + v[i].w;
    }
#pragma unroll
    for (int o2 = 16; o2; o2 >>= 1) s += __shfl_xor_sync(0xffffffffu, s, o2);
    if ((tid & 31) == 0) sbuf[tid >> 5] = s;
    __syncthreads();
    const float mean = (sbuf[0] + sbuf[1] + sbuf[2] + sbuf[3]) * (1.f / C);
    __syncthreads();

    float vs = 0.f;
#pragma unroll
    for (int i = 0; i < NV; i++) {
        float dx;
        dx = v[i].x - mean; vs += dx * dx;
        dx = v[i].y - mean; vs += dx * dx;
        dx = v[i].z - mean; vs += dx * dx;
        dx = v[i].w - mean; vs += dx * dx;
    }
#pragma unroll
    for (int o2 = 16; o2; o2 >>= 1) vs += __shfl_xor_sync(0xffffffffu, vs, o2);
    if ((tid & 31) == 0) sbuf[tid >> 5] = vs;
    __syncthreads();
    const float var  = (sbuf[0] + sbuf[1] + sbuf[2] + sbuf[3]) * (1.f / C);
    const float rstd = 1.f / sqrtf(var + 1e-5f);

    __half* orow = out + (size_t)blockIdx.x * C;
#pragma unroll
    for (int i = 0; i < NV; i++) {
        const int idx = (i * 128 + tid) * 4;
        float4 gg = *(const float4*)(g + idx);
        float4 bb = *(const float4*)(b + idx);
        float4 r;
        r.x = (v[i].x - mean) * rstd * gg.x + bb.x;
        r.y = (v[i].y - mean) * rstd * gg.y + bb.y;
        r.z = (v[i].z - mean) * rstd * gg.z + bb.z;
        r.w = (v[i].w - mean) * rstd * gg.w + bb.w;
        if (RELU) {
            r.x = fmaxf(r.x, 0.f); r.y = fmaxf(r.y, 0.f);
            r.z = fmaxf(r.z, 0.f); r.w = fmaxf(r.w, 0.f);
        }
        __half2 h0 = __float22half2_rn(make_float2(r.x, r.y));
        __half2 h1 = __float22half2_rn(make_float2(r.z, r.w));
        *(__half2*)(orow + idx)     = h0;
        *(__half2*)(orow + idx + 2) = h1;
    }
}

// ---------------- banded attention: 1 block / query, 1 warp / head ----------------
// Phase A: mask+gbias computed ONCE per (n,m) pair (head-independent), in smem.
// Phase B: per-head single pass with online softmax (rescale on new max).
// Skipping masked entries is exact: exp(-1e9 - max) == 0 in fp32.
__global__ __launch_bounds__(128) void attn_kernel(
    const float* __restrict__ pos, const float* __restrict__ ori,
    const int* __restrict__ batch)
{
    const int n    = blockIdx.x;
    const int tid  = threadIdx.x;
    const int h    = tid >> 5;
    const int lane = tid & 31;
    __shared__ float base[2 * LWIN + 1];

    const int m0  = (n - LWIN < 0) ? 0 : n - LWIN;
    const int m1  = (n + LWIN > N_TOK - 1) ? N_TOK - 1 : n + LWIN;
    const int cnt = m1 - m0 + 1;

    if (tid < cnt) {
        const int m = m0 + tid;
        const float dx = pos[3 * m]     - pos[3 * n];
        const float dy = pos[3 * m + 1] - pos[3 * n + 1];
        const float dz = pos[3 * m + 2] - pos[3 * n + 2];
        const bool ok = (batch[m] == batch[n]) && (dx * dx + dy * dy + dz * dz <= 1.0f);
        base[tid] = ok ? (ori[3 * n]     * ori[3 * m] +
                          ori[3 * n + 1] * ori[3 * m + 1] +
                          ori[3 * n + 2] * ori[3 * m + 2])
                       : -1e30f;
    }
    __syncthreads();

    const float* q     = g_qkv + ((size_t)h * N_TOK + n) * HIDD;
    const float* kbase = g_qkv + ((size_t)(NH + h)) * (size_t)N_TOK * HIDD;
    const float* vbase = g_qkv + ((size_t)(2 * NH + h)) * (size_t)N_TOK * HIDD;

    const float4 q4 = *(const float4*)(q + lane * 4);

    float  mx  = -1e30f;
    float  sum = 0.f;
    float4 acc = make_float4(0.f, 0.f, 0.f, 0.f);

    for (int j = 0; j < cnt; j++) {
        const float b = base[j];
        if (b < -1e29f) continue;
        const int m = m0 + j;

        float4 k4 = *(const float4*)(kbase + (size_t)m * HIDD + lane * 4);
        float d = q4.x * k4.x + q4.y * k4.y + q4.z * k4.z + q4.w * k4.w;
#pragma unroll
        for (int o2 = 16; o2; o2 >>= 1) d += __shfl_xor_sync(0xffffffffu, d, o2);
        const float s = d * 0.08838834764831843f + b;

        float4 v4 = *(const float4*)(vbase + (size_t)m * HIDD + lane * 4);
        if (s > mx) {
            const float corr = __expf(mx - s);
            sum = sum * corr + 1.f;
            acc.x = acc.x * corr + v4.x;
            acc.y = acc.y * corr + v4.y;
            acc.z = acc.z * corr + v4.z;
            acc.w = acc.w * corr + v4.w;
            mx = s;
        } else {
            const float p = __expf(s - mx);
            sum += p;
            acc.x = fmaf(p, v4.x, acc.x);
            acc.y = fmaf(p, v4.y, acc.y);
            acc.z = fmaf(p, v4.z, acc.z);
            acc.w = fmaf(p, v4.w, acc.w);
        }
    }

    const float inv = 1.f / sum;
    __half* op = g_oh + ((size_t)h * N_TOK + n) * HIDD;
    *(__half2*)(op + lane * 4)     = __float22half2_rn(make_float2(acc.x * inv, acc.y * inv));
    *(__half2*)(op + lane * 4 + 2) = __float22half2_rn(make_float2(acc.z * inv, acc.w * inv));
}

// ---------------- launch ----------------
extern "C" void kernel_launch(void* const* d_in, const int* in_sizes, int n_in,
                              void* d_out, int out_size)
{
    const float* x     = (const float*)d_in[0];
    const float* pos   = (const float*)d_in[1];
    const float* ori   = (const float*)d_in[2];
    // d_in[3] = seq == arange(N): the |ds|<=48 term is handled by the index band.
    const int*   batch = (const int*)d_in[4];
    const float* ln1_g = (const float*)d_in[5];
    const float* ln1_b = (const float*)d_in[6];
    const float* ln2_g = (const float*)d_in[7];
    const float* ln2_b = (const float*)d_in[8];
    const float* Wq    = (const float*)d_in[9];
    const float* Wk    = (const float*)d_in[10];
    const float* Wv    = (const float*)d_in[11];
    const float* Wo    = (const float*)d_in[12];
    const float* lnm_g = (const float*)d_in[13];
    const float* lnm_b = (const float*)d_in[14];
    const float* W1    = (const float*)d_in[15];
    const float* W2    = (const float*)d_in[16];
    float* out = (float*)d_out;

    __half *p_xnh, *p_h1h, *p_midnh, *p_wh;
    float  *p_x1, *p_mid;
    cudaGetSymbolAddress((void**)&p_xnh,   g_xnh);
    cudaGetSymbolAddress((void**)&p_x1,    g_x1);
    cudaGetSymbolAddress((void**)&p_h1h,   g_h1h);
    cudaGetSymbolAddress((void**)&p_mid,   g_mid);
    cudaGetSymbolAddress((void**)&p_midnh, g_midnh);
    cudaGetSymbolAddress((void**)&p_wh,    g_wh);

    // allow 110.6KB dynamic smem on the GEMM kernels (idempotent, capture-safe)
    static bool attr_done = false;
    if (!attr_done) {
        cudaFuncSetAttribute(sgemm_f16_kernel,
                             cudaFuncAttributeMaxDynamicSharedMemorySize, GEMM_SMEM);
        cudaFuncSetAttribute(qkv_kernel,
                             cudaFuncAttributeMaxDynamicSharedMemorySize, GEMM_SMEM);
        cudaFuncSetAttribute(wo_kernel,
                             cudaFuncAttributeMaxDynamicSharedMemorySize, GEMM_SMEM);
        attr_done = true;
    }

    // 0. transpose+convert all weights to fp16 [N][K] (single launch, 2880 tiles)
    transpose_all_kernel<<<2880, 256>>>(Wq, Wk, Wv, Wo, W1, W2);

    // 1. xn = LN1(x), fp16
    ln_kernel<512, false><<<N_TOK, 128>>>(x, ln1_g, ln1_b, p_xnh);

    // 2. Q/K/V projections (batched, 384 CTAs, fp16 m16n8k16 + ldmatrix, BK=64)
    qkv_kernel<<<dim3(1, N_TOK / 128, 12), 256, GEMM_SMEM>>>();

    // 3. banded attention (single pass, shared mask/bias; fp32 math, fp16 output)
    attn_kernel<<<N_TOK, 128>>>(pos, ori, batch);

    // 4. x1 = concat_h(o_h @ Wo_h) + x
    wo_kernel<<<dim3(1, N_TOK / 128, 4), 256, GEMM_SMEM>>>(x);

    // 5. h1 = LN2(x1), fp16
    ln_kernel<512, false><<<N_TOK, 128>>>(p_x1, ln2_g, ln2_b, p_h1h);

    // 6. mid = h1 @ W1
    sgemm_f16_kernel<<<dim3(MIDC / 128, N_TOK / 128), 256, GEMM_SMEM>>>(
        p_h1h, CIN, p_wh + OW1, CIN, p_mid, MIDC, nullptr, CIN);

    // 7. midn = relu(LN_mid(mid)), fp16
    ln_kernel<2048, true><<<N_TOK, 128>>>(p_mid, lnm_g, lnm_b, p_midnh);

    // 8. out = midn @ W2 + x1
    sgemm_f16_kernel<<<dim3(COUT / 128, N_TOK / 128), 256, GEMM_SMEM>>>(
        p_midnh, MIDC, p_wh + OW2, MIDC, out, COUT, p_x1, MIDC);
}